// round 5
// baseline (speedup 1.0000x reference)
#include <cuda_runtime.h>

// Scratch (no device allocations allowed) — reset by the last block each run,
// so every kernel_launch invocation is deterministic.
static __device__ double   g_acc   = 0.0;
static __device__ unsigned g_count = 0;

__device__ __forceinline__ float fast_tanh(float x) {
    float r;
    asm("tanh.approx.f32 %0, %1;" : "=f"(r) : "f"(x));
    return r;
}

// Math (per row, K=16):
//   row = lse(w + comp) - lse(w) = log(S2') - log(S1) - ln4    (unshifted)
//   S1  = sum_k e^{w_k}
//   S2' = sum_k e^{w_k} * (1/s_k) * (1 - tanh^2(z_k/2)),  z = (t - loc)/s
// using e^m/(1+e^m)^2 = (1 - tanh^2(z/2))/4  (even in z, no fabs needed).
//
// Layout: ONE row per thread. 12 independent LDG.128 + 1 LDG.32 batched up
// front (MLP~13), no cross-lane shuffles. 4 consecutive per-thread float4s
// keep warp accesses fully dense (2KB contiguous per tensor per warp-iter).
__global__ __launch_bounds__(256, 4) void MixtureOfLogistics_kernel(
    const float* __restrict__ weight,
    const float* __restrict__ loc,
    const float* __restrict__ scale,
    const float* __restrict__ targets,
    float* __restrict__ out,
    int n_rows, double inv_n)
{
    const int tid    = blockIdx.x * blockDim.x + threadIdx.x;
    const int stride = gridDim.x * blockDim.x;

    float acc = 0.0f;

    for (int row = tid; row < n_rows; row += stride) {
        const float4* wp = reinterpret_cast<const float4*>(weight + (size_t)row * 16);
        const float4* lp = reinterpret_cast<const float4*>(loc    + (size_t)row * 16);
        const float4* sp = reinterpret_cast<const float4*>(scale  + (size_t)row * 16);

        // Front-batched independent loads: 12x LDG.128 + 1x LDG.32.
        const float4 w0 = wp[0], w1 = wp[1], w2 = wp[2], w3 = wp[3];
        const float4 l0 = lp[0], l1 = lp[1], l2 = lp[2], l3 = lp[3];
        const float4 s0 = sp[0], s1 = sp[1], s2 = sp[2], s3 = sp[3];
        const float t = __ldg(targets + row);

        const float w[16] = {w0.x,w0.y,w0.z,w0.w, w1.x,w1.y,w1.z,w1.w,
                             w2.x,w2.y,w2.z,w2.w, w3.x,w3.y,w3.z,w3.w};
        const float l[16] = {l0.x,l0.y,l0.z,l0.w, l1.x,l1.y,l1.z,l1.w,
                             l2.x,l2.y,l2.z,l2.w, l3.x,l3.y,l3.z,l3.w};
        const float s[16] = {s0.x,s0.y,s0.z,s0.w, s1.x,s1.y,s1.z,s1.w,
                             s2.x,s2.y,s2.z,s2.w, s3.x,s3.y,s3.z,s3.w};

        float S1 = 0.0f, S2 = 0.0f;
        #pragma unroll
        for (int c = 0; c < 16; c++) {
            float rs = __fdividef(1.0f, s[c]);          // MUFU rcp
            float th = fast_tanh((t - l[c]) * rs * 0.5f); // MUFU tanh
            float ew = __expf(w[c]);                    // MUFU ex2
            S1 += ew;
            S2 = fmaf(ew * rs, fmaf(-th, th, 1.0f), S2);
        }

        S2 = fmaxf(S2, 1e-37f);                         // underflow guard
        // log(S2/4 / S1) = log(S2/S1) - ln(4)
        acc += __logf(__fdividef(S2, S1)) - 1.3862943611f;
    }

    // Full warp reduction (every lane holds a partial).
    #pragma unroll
    for (int off = 16; off > 0; off >>= 1)
        acc += __shfl_xor_sync(0xffffffffu, acc, off);

    __shared__ float warp_part[8];
    const int warp = threadIdx.x >> 5;
    const int lane = threadIdx.x & 31;
    if (lane == 0) warp_part[warp] = acc;
    __syncthreads();

    if (warp == 0) {
        float v = (lane < (int)(blockDim.x >> 5)) ? warp_part[lane] : 0.0f;
        #pragma unroll
        for (int off = 4; off > 0; off >>= 1)
            v += __shfl_xor_sync(0xffffffffu, v, off);

        if (lane == 0) {
            atomicAdd(&g_acc, (double)v);
            __threadfence();
            unsigned done = atomicAdd(&g_count, 1u);
            if (done == gridDim.x - 1) {
                out[0] = (float)(g_acc * inv_n);
                g_acc   = 0.0;     // reset for next deterministic replay
                g_count = 0u;
                __threadfence();
            }
        }
    }
}

extern "C" void kernel_launch(void* const* d_in, const int* in_sizes, int n_in,
                              void* d_out, int out_size) {
    const float* weight  = (const float*)d_in[0];
    const float* loc     = (const float*)d_in[1];
    const float* scale   = (const float*)d_in[2];
    const float* targets = (const float*)d_in[3];
    float* out = (float*)d_out;

    const int n_rows = in_sizes[3];          // B*T = 2,097,152
    const double inv_n = 1.0 / (double)n_rows;

    // One resident wave: 148 SMs x 4 blocks/SM (64-reg cap via launch_bounds).
    MixtureOfLogistics_kernel<<<592, 256>>>(weight, loc, scale, targets, out,
                                            n_rows, inv_n);
}